// round 5
// baseline (speedup 1.0000x reference)
#include <cuda_runtime.h>
#include <cuda_bf16.h>
#include <math.h>
#include <stdint.h>

// Problem dims
#define BB   128
#define TT   512
#define FF   784
#define HH   256
#define NG   1024   // 4*H
#define CC   10
#define BN_EPS 1e-3f

// K1 GEMM tiling: 128x128 CTA tile, BK=16 (784 = 49*16)
#define BKC  16
#define NCHK (FF / BKC)   // 49

// Scratch (device globals; no runtime allocation allowed)
__device__ float  g_xw[(size_t)BB * TT * NG];    // 256 MiB
__device__ float  g_hs[(size_t)BB * TT * HH];    //  64 MiB
__device__ float4 g_rw[(size_t)HH * HH];         //   1 MiB packed rec weights
__device__ __nv_bfloat16 g_bhi[(size_t)NG * FF]; // 1.6 MiB: kernel^T hi, [n][k]
__device__ __nv_bfloat16 g_blo[(size_t)NG * FF]; // 1.6 MiB: kernel^T lo

// ---------------------------------------------------------------------------
// helpers
// ---------------------------------------------------------------------------
__device__ __forceinline__ uint32_t smem_u32(const void* p) {
    uint32_t a;
    asm("{ .reg .u64 t; cvta.to.shared.u64 t, %1; cvt.u32.u64 %0, t; }" : "=r"(a) : "l"(p));
    return a;
}
__device__ __forceinline__ void f2bf_hilo(float x, uint16_t& h, uint16_t& l) {
    __nv_bfloat16 hb = __float2bfloat16(x);
    h = __bfloat16_as_ushort(hb);
    l = __bfloat16_as_ushort(__float2bfloat16(x - __bfloat162float(hb)));
}
__device__ __forceinline__ float fsig(float x) {
    return __fdividef(1.f, 1.f + __expf(-x));
}
__device__ __forceinline__ float ftanh(float x) {
    x = fminf(fmaxf(x, -15.f), 15.f);
    float e = __expf(-2.f * x);
    return __fdividef(1.f - e, 1.f + e);
}
__device__ __forceinline__ void mma_bf16(float* d, const uint32_t* a, const uint32_t* b) {
    asm volatile(
        "mma.sync.aligned.m16n8k16.row.col.f32.bf16.bf16.f32 "
        "{%0,%1,%2,%3}, {%4,%5,%6,%7}, {%8,%9}, {%0,%1,%2,%3};"
        : "+f"(d[0]), "+f"(d[1]), "+f"(d[2]), "+f"(d[3])
        : "r"(a[0]), "r"(a[1]), "r"(a[2]), "r"(a[3]), "r"(b[0]), "r"(b[1]));
}

// ---------------------------------------------------------------------------
// K0a: pack rec_kernel [H,4H] -> rw[k][u] float4 {i,f,c,o}
// ---------------------------------------------------------------------------
__global__ void pack_rec_kernel(const float* __restrict__ rec, float4* __restrict__ rw)
{
    int idx = blockIdx.x * blockDim.x + threadIdx.x;
    if (idx >= HH * HH) return;
    int k = idx >> 8;
    int u = idx & 255;
    const float* r = rec + (size_t)k * NG;
    rw[idx] = make_float4(r[u], r[HH + u], r[2 * HH + u], r[3 * HH + u]);
}

// ---------------------------------------------------------------------------
// K0b: split + transpose kernel [F,4H] -> g_bhi/g_blo [n][k] bf16
// ---------------------------------------------------------------------------
__global__ void pack_b_kernel(const float* __restrict__ Bm)
{
    int idx = blockIdx.x * blockDim.x + threadIdx.x;
    if (idx >= NG * FF) return;
    int n = idx / FF;
    int k = idx % FF;
    float v = Bm[(size_t)k * NG + n];
    uint16_t h, l;
    f2bf_hilo(v, h, l);
    g_bhi[idx] = __ushort_as_bfloat16(h);
    g_blo[idx] = __ushort_as_bfloat16(l);
}

// ---------------------------------------------------------------------------
// K1: xw = x @ kernel + bias via mma.sync bf16x3 (hi*hi + hi*lo + lo*hi).
// CTA: 256 threads = 8 warps (4 m x 2 n), warp tile 32x64, BK=16, 49 chunks.
// ---------------------------------------------------------------------------
#define SROW 48   // bytes per smem row (16 bf16 = 32B used + 16B pad)

__global__ __launch_bounds__(256, 1)
void gemm_mma_kernel(const float* __restrict__ A,     // x: [B*T, FF]
                     const float* __restrict__ bias)  // [NG]
{
    __shared__ __align__(16) char sm[4 * 128 * SROW];   // 24 KB
    char* As_hi = sm;
    char* As_lo = sm + 128 * SROW;
    char* Bs_hi = sm + 2 * 128 * SROW;
    char* Bs_lo = sm + 3 * 128 * SROW;

    const int tid  = threadIdx.x;
    const int lane = tid & 31;
    const int wid  = tid >> 5;
    const int bx   = blockIdx.x;    // n tile (8)
    const int by   = blockIdx.y;    // m tile (512)

    const int m0w = (wid & 3) * 32;   // warp m origin
    const int n0w = (wid >> 2) * 64;  // warp n origin
    const int g   = lane >> 2;        // fragment group row
    const int tq  = lane & 3;         // fragment quad col

    float d[2][8][4];
#pragma unroll
    for (int i = 0; i < 2; i++)
#pragma unroll
        for (int j = 0; j < 8; j++)
#pragma unroll
            for (int q = 0; q < 4; q++) d[i][j][q] = 0.f;

    const int s_row  = tid >> 1;
    const int s_half = tid & 1;
    const float* Ag = A + (size_t)(by * 128 + s_row) * FF + s_half * 8;
    const char*  BgH = (const char*)g_bhi + ((size_t)(bx * 128 + s_row) * FF + s_half * 8) * 2;
    const char*  BgL = (const char*)g_blo + ((size_t)(bx * 128 + s_row) * FF + s_half * 8) * 2;
    char* sAh = As_hi + s_row * SROW + s_half * 16;
    char* sAl = As_lo + s_row * SROW + s_half * 16;
    char* sBh = Bs_hi + s_row * SROW + s_half * 16;
    char* sBl = Bs_lo + s_row * SROW + s_half * 16;

    float4 av0 = *(const float4*)(Ag);
    float4 av1 = *(const float4*)(Ag + 4);
    uint4  bvh = *(const uint4*)(BgH);
    uint4  bvl = *(const uint4*)(BgL);

    for (int ic = 0; ic < NCHK; ic++) {
        {
            float f[8] = {av0.x, av0.y, av0.z, av0.w, av1.x, av1.y, av1.z, av1.w};
            uint16_t h[8], l[8];
#pragma unroll
            for (int e = 0; e < 8; e++) f2bf_hilo(f[e], h[e], l[e]);
            uint4 hp, lp;
            hp.x = ((uint32_t)h[1] << 16) | h[0]; hp.y = ((uint32_t)h[3] << 16) | h[2];
            hp.z = ((uint32_t)h[5] << 16) | h[4]; hp.w = ((uint32_t)h[7] << 16) | h[6];
            lp.x = ((uint32_t)l[1] << 16) | l[0]; lp.y = ((uint32_t)l[3] << 16) | l[2];
            lp.z = ((uint32_t)l[5] << 16) | l[4]; lp.w = ((uint32_t)l[7] << 16) | l[6];
            *(uint4*)sAh = hp;
            *(uint4*)sAl = lp;
            *(uint4*)sBh = bvh;
            *(uint4*)sBl = bvl;
        }
        __syncthreads();

        if (ic + 1 < NCHK) {
            const int k0 = (ic + 1) * BKC;
            av0 = *(const float4*)(Ag + k0);
            av1 = *(const float4*)(Ag + k0 + 4);
            bvh = *(const uint4*)(BgH + (size_t)k0 * 2);
            bvl = *(const uint4*)(BgL + (size_t)k0 * 2);
        }

        uint32_t ah[2][4], al[2][4];
#pragma unroll
        for (int i = 0; i < 2; i++) {
            const char* ab = As_hi + (m0w + i * 16 + g) * SROW + tq * 4;
            ah[i][0] = *(const uint32_t*)(ab);
            ah[i][1] = *(const uint32_t*)(ab + 8 * SROW);
            ah[i][2] = *(const uint32_t*)(ab + 16);
            ah[i][3] = *(const uint32_t*)(ab + 8 * SROW + 16);
            const char* lb = As_lo + (m0w + i * 16 + g) * SROW + tq * 4;
            al[i][0] = *(const uint32_t*)(lb);
            al[i][1] = *(const uint32_t*)(lb + 8 * SROW);
            al[i][2] = *(const uint32_t*)(lb + 16);
            al[i][3] = *(const uint32_t*)(lb + 8 * SROW + 16);
        }
#pragma unroll
        for (int j = 0; j < 8; j++) {
            const char* bb = Bs_hi + (n0w + j * 8 + g) * SROW + tq * 4;
            const char* bl = Bs_lo + (n0w + j * 8 + g) * SROW + tq * 4;
            uint32_t bhf[2], blf[2];
            bhf[0] = *(const uint32_t*)(bb);
            bhf[1] = *(const uint32_t*)(bb + 16);
            blf[0] = *(const uint32_t*)(bl);
            blf[1] = *(const uint32_t*)(bl + 16);
#pragma unroll
            for (int i = 0; i < 2; i++) {
                mma_bf16(d[i][j], ah[i], bhf);
                mma_bf16(d[i][j], ah[i], blf);
                mma_bf16(d[i][j], al[i], bhf);
            }
        }
        __syncthreads();
    }

#pragma unroll
    for (int j = 0; j < 8; j++) {
        const int col = bx * 128 + n0w + j * 8 + tq * 2;
        const float b0 = bias[col];
        const float b1 = bias[col + 1];
#pragma unroll
        for (int i = 0; i < 2; i++) {
            const int row = by * 128 + m0w + i * 16 + g;
            float2 v0 = make_float2(d[i][j][0] + b0, d[i][j][1] + b1);
            float2 v1 = make_float2(d[i][j][2] + b0, d[i][j][3] + b1);
            *(float2*)(g_xw + (size_t)row * NG + col)       = v0;
            *(float2*)(g_xw + (size_t)(row + 8) * NG + col) = v1;
        }
    }
}

// ---------------------------------------------------------------------------
// K2: peephole LSTM recurrence — 8-CTA clusters, SMEM-resident weights.
// Cluster = 8 batch rows x 256 units. CTA rank r owns units [32r, 32r+32);
// its 128 KB weight slice lives in dynamic smem (loaded once).
// Thread = (unit, batch): warp w covers units [4w,4w+4) x 8 batches.
//   lane = us*8 + b  (us = local unit 0..3, b = batch 0..7)
// h rows padded to 260 floats -> conflict-free 8-batch LDS.
// xw gate inputs for t+1 prefetched before the k-loop (added at the end).
// ---------------------------------------------------------------------------
#define KBPC    8
#define CLU     8
#define UPC     32                       // units per CTA
#define HSTRIDE 260                      // floats per (buf,batch) row
#define WS_BYTES (HH * UPC * 16)         // 131072
#define HBUF_FLOATS (KBPC * HSTRIDE)     // 2080
#define HBUF_BYTES  (HBUF_FLOATS * 4)    // 8320
#define K2_SMEM (WS_BYTES + 2 * HBUF_BYTES)   // 147712

__global__ __launch_bounds__(256, 1) __cluster_dims__(CLU, 1, 1)
void lstm_cluster_kernel(const float*  __restrict__ xw,
                         const float4* __restrict__ rw,
                         const float*  __restrict__ wci_p,
                         const float*  __restrict__ wcf_p,
                         const float*  __restrict__ wco_p,
                         float* __restrict__ hs)
{
    extern __shared__ __align__(16) char sm2[];
    float4* ws = (float4*)sm2;                 // [HH][UPC]
    float*  hb = (float*)(sm2 + WS_BYTES);     // [2][KBPC][HSTRIDE]

    const int tid = threadIdx.x;
    uint32_t rank;
    asm("mov.u32 %0, %%cluster_ctarank;" : "=r"(rank));
    const int group = blockIdx.x / CLU;
    const int b0    = group * KBPC;

    const int w  = tid >> 5;
    const int l  = tid & 31;
    const int us = l >> 3;          // local unit within warp (0..3)
    const int b  = l & 7;           // batch (0..7)
    const int ul = w * 4 + us;      // unit within CTA (0..31)
    const int u  = (int)rank * UPC + ul;   // global unit

    // load weight slice: ws[k][ul] = rw[k*256 + rank*32 + ul]
    for (int idx = tid; idx < HH * UPC; idx += 256) {
        int k  = idx >> 5;
        int uu = idx & 31;
        ws[idx] = rw[(k << 8) + (int)rank * UPC + uu];
    }
    // zero both h buffers
    for (int i = tid; i < 2 * HBUF_FLOATS; i += 256) hb[i] = 0.f;

    const float wci = wci_p[u];
    const float wcf = wcf_p[u];
    const float wco = wco_p[u];

    // remote addresses (buffer 0 slot) of my h value in all 8 CTAs
    uint32_t rem[CLU];
    {
        uint32_t l0 = smem_u32(hb) + (uint32_t)(b * HSTRIDE + u) * 4u;
#pragma unroll
        for (int r = 0; r < CLU; r++)
            asm("mapa.shared::cluster.u32 %0, %1, %2;" : "=r"(rem[r]) : "r"(l0), "r"(r));
    }

    asm volatile("barrier.cluster.arrive.aligned;" ::: "memory");
    asm volatile("barrier.cluster.wait.aligned;"   ::: "memory");

    const float* xp = xw + (size_t)(b0 + b) * TT * NG;
    float* hp = hs + (size_t)(b0 + b) * TT * HH + u;

    float c = 0.f;
    float xv0 = xp[u], xv1 = xp[HH + u], xv2 = xp[2 * HH + u], xv3 = xp[3 * HH + u];

    for (int t = 0; t < TT; t++) {
        // prefetch next step's gate inputs (overlaps the whole k-loop)
        const float* xn = (t + 1 < TT) ? xp + NG : xp;
        float n0 = xn[u];
        float n1 = xn[HH + u];
        float n2 = xn[2 * HH + u];
        float n3 = xn[3 * HH + u];

        const int rb = t & 1;
        const float4* h4 = (const float4*)(hb + rb * HBUF_FLOATS + b * HSTRIDE);

        float a0 = 0.f, a1 = 0.f, a2 = 0.f, a3 = 0.f;
#pragma unroll 4
        for (int k4 = 0; k4 < HH / 4; k4++) {
            float4 hv = h4[k4];
            float4 w0 = ws[(k4 * 4 + 0) * UPC + ul];
            float4 w1 = ws[(k4 * 4 + 1) * UPC + ul];
            float4 w2 = ws[(k4 * 4 + 2) * UPC + ul];
            float4 w3 = ws[(k4 * 4 + 3) * UPC + ul];
            a0 += w0.x * hv.x; a1 += w0.y * hv.x; a2 += w0.z * hv.x; a3 += w0.w * hv.x;
            a0 += w1.x * hv.y; a1 += w1.y * hv.y; a2 += w1.z * hv.y; a3 += w1.w * hv.y;
            a0 += w2.x * hv.z; a1 += w2.y * hv.z; a2 += w2.z * hv.z; a3 += w2.w * hv.z;
            a0 += w3.x * hv.w; a1 += w3.y * hv.w; a2 += w3.z * hv.w; a3 += w3.w * hv.w;
        }

        float ig = fsig(a0 + xv0 + c * wci);
        float fg = fsig(a1 + xv1 + c * wcf);
        float cn = fg * c + ig * ftanh(a2 + xv2);
        float og = fsig(a3 + xv3 + cn * wco);
        float hn = og * ftanh(cn);
        c = cn;

        // write h into the other buffer of all 8 CTAs
        const uint32_t boff = (uint32_t)((rb ^ 1) * HBUF_BYTES);
#pragma unroll
        for (int r = 0; r < CLU; r++)
            asm volatile("st.shared::cluster.f32 [%0], %1;"
                         :: "r"(rem[r] + boff), "f"(hn) : "memory");

        hp[0] = hn;
        hp += HH;
        xp = xn;
        xv0 = n0; xv1 = n1; xv2 = n2; xv3 = n3;

        asm volatile("barrier.cluster.arrive.aligned;" ::: "memory");
        asm volatile("barrier.cluster.wait.aligned;"   ::: "memory");
    }
}

// ---------------------------------------------------------------------------
// K3: BN(inference) -> tanh -> dense head.
// ---------------------------------------------------------------------------
__global__ __launch_bounds__(256)
void head_kernel(const float* __restrict__ hs,
                 const float* __restrict__ gamma,
                 const float* __restrict__ beta,
                 const float* __restrict__ mean,
                 const float* __restrict__ var,
                 const float* __restrict__ fc,
                 float* __restrict__ out)
{
    const int warp = (blockIdx.x * blockDim.x + threadIdx.x) >> 5;
    const int lane = threadIdx.x & 31;
    if (warp >= BB * TT) return;

    const float* hrow = hs + (size_t)warp * HH;
    float acc[CC];
#pragma unroll
    for (int c = 0; c < CC; c++) acc[c] = 0.f;

#pragma unroll
    for (int kk = 0; kk < HH / 32; kk++) {
        int k = kk * 32 + lane;
        float s = rsqrtf(var[k] + BN_EPS) * gamma[k];
        float v = tanhf((hrow[k] - mean[k]) * s + beta[k]);
#pragma unroll
        for (int c = 0; c < CC; c++)
            acc[c] += v * fc[k * CC + c];
    }
#pragma unroll
    for (int c = 0; c < CC; c++) {
#pragma unroll
        for (int off = 16; off > 0; off >>= 1)
            acc[c] += __shfl_xor_sync(0xffffffffu, acc[c], off);
    }
    if (lane == 0) {
        float* orow = out + (size_t)warp * CC;
#pragma unroll
        for (int c = 0; c < CC; c++) orow[c] = acc[c];
    }
}

// ---------------------------------------------------------------------------
extern "C" void kernel_launch(void* const* d_in, const int* in_sizes, int n_in,
                              void* d_out, int out_size)
{
    const float* x      = (const float*)d_in[0];
    const float* kernel = (const float*)d_in[1];
    const float* rec    = (const float*)d_in[2];
    const float* bias   = (const float*)d_in[3];
    const float* w_ci   = (const float*)d_in[4];
    const float* w_cf   = (const float*)d_in[5];
    const float* w_co   = (const float*)d_in[6];
    const float* gamma  = (const float*)d_in[7];
    const float* beta   = (const float*)d_in[8];
    const float* mmean  = (const float*)d_in[9];
    const float* mvar   = (const float*)d_in[10];
    const float* fc_w   = (const float*)d_in[11];
    float* out = (float*)d_out;

    float*  xw_p;
    float*  hs_p;
    float4* rw_p;
    cudaGetSymbolAddress((void**)&xw_p, g_xw);
    cudaGetSymbolAddress((void**)&hs_p, g_hs);
    cudaGetSymbolAddress((void**)&rw_p, g_rw);

    cudaFuncSetAttribute(lstm_cluster_kernel,
                         cudaFuncAttributeMaxDynamicSharedMemorySize, K2_SMEM);

    // K0: packing
    pack_rec_kernel<<<(HH * HH + 255) / 256, 256>>>(rec, rw_p);
    pack_b_kernel<<<((size_t)NG * FF + 255) / 256, 256>>>(kernel);

    // K1: HMMA input-projection GEMM
    dim3 g1(NG / 128, (BB * TT) / 128);
    gemm_mma_kernel<<<g1, 256>>>(x, bias);

    // K2: recurrence, 16 clusters x 8 CTAs, smem-resident weights
    lstm_cluster_kernel<<<(BB / KBPC) * CLU, 256, K2_SMEM>>>(
        xw_p, rw_p, w_ci, w_cf, w_co, hs_p);

    // K3: head
    int rows = BB * TT;
    head_kernel<<<(rows * 32 + 255) / 256, 256>>>(hs_p, gamma, beta, mmean, mvar, fc_w, out);
}